// round 17
// baseline (speedup 1.0000x reference)
#include <cuda_runtime.h>
#include <cstdint>
#include <cstdio>

#define SEQ_LEN 2048
#define BATCHSZ 32
#define HIDDEN  512
#define VOCAB   32000
#define GWID    2048   /* 4*HIDDEN */
#define NCTA    128    /* 64 CTAs per direction */

typedef unsigned long long u64;

// packed fp32x2 FMA (sm_100+): d = a*b + c on both lanes
#define FMA2(d, a, b, c) \
    asm("fma.rn.f32x2 %0, %1, %2, %3;" : "=l"(d) : "l"(a), "l"(b), "l"(c))
#define SPLAT2(d, f) \
    asm("mov.b64 %0, {%1, %1};" : "=l"(d) : "f"(f))
#define UNPK2(lo, hi, d) \
    asm("mov.b64 {%0, %1}, %2;" : "=f"(lo), "=f"(hi) : "l"(d))

#define CPASYNC16(dst_u32, src_ptr) \
    asm volatile("cp.async.cg.shared.global [%0], [%1], 16;" :: "r"(dst_u32), "l"(src_ptr))
#define CPCOMMIT() asm volatile("cp.async.commit_group;")
#define CPWAIT(n)  asm volatile("cp.async.wait_group %0;" :: "n"(n))

__device__ __forceinline__ float sigmoid_fast(float x) {
    return __fdividef(1.0f, 1.0f + __expf(-x));
}
__device__ __forceinline__ float tanh_fast(float x) {
    // 2/(1+e^-2x) - 1 : saturates correctly at +/-inf
    return __fdividef(2.0f, 1.0f + __expf(-2.0f * x)) - 1.0f;
}

// ---------------- device scratch (static allocation: allowed) ----------------
__device__ float    g_table[(size_t)2 * VOCAB * GWID];   // 524 MB gate bias table
__device__ float    g_hbuf[2][2][HIDDEN * BATCHSZ];      // [dir][phase][r*32+b]
__device__ unsigned g_prog[2][64][32];                   // per-CTA progress (128B stride)
__device__ int      g_tok64;

// ---------------- init ---------------------------------------------------------
__global__ void init_kernel(const int* __restrict__ tok32, const float* __restrict__ h0) {
    int i = blockIdx.x * blockDim.x + threadIdx.x;
    if (i < 2 * 64 * 32) ((unsigned*)g_prog)[i] = 0;
    if (i < 2 * HIDDEN * BATCHSZ) {
        int d  = i >> 14;
        int rb = i & 16383;
        int b  = rb & 31;
        int r  = rb >> 5;
        g_hbuf[d][0][rb] = h0[b * HIDDEN + r];
    }
    if (i == 0) {
        int nz = 0;
        for (int j = 0; j < 128; ++j) nz |= tok32[2 * j + 1];
        g_tok64 = (nz == 0) ? 1 : 0;
    }
}

// ---------------- vocab gate-table GEMM: 128x128 tile, K16, double-buffered -----
__global__ void __launch_bounds__(256, 2) gx_gemm_kernel(
    const float* __restrict__ E,
    const float* __restrict__ wx_f, const float* __restrict__ bx_f, const float* __restrict__ bh_f,
    const float* __restrict__ wx_b, const float* __restrict__ bx_b, const float* __restrict__ bh_b)
{
    const int d  = blockIdx.z;
    const float* Wx = d ? wx_b : wx_f;
    const float* bx = d ? bx_b : bx_f;
    const float* bh = d ? bh_b : bh_f;
    const int c0 = blockIdx.x * 128;
    const int v0 = blockIdx.y * 128;

    __shared__ float As[2][16][132];   // [k][row] transposed, padded
    __shared__ float Bs[2][16][128];   // [k][c]

    const int tid = threadIdx.x;
    const int tx  = tid & 15;          // cols tx*8..tx*8+8
    const int ty  = tid >> 4;          // rows ty*8..ty*8+8

    u64 acc2[4][8];                    // row-pair p x col j
#pragma unroll
    for (int p = 0; p < 4; ++p)
#pragma unroll
        for (int j = 0; j < 8; ++j) acc2[p][j] = 0ull;

    float4 aR[2], bR[2];
    const int arow0 = tid >> 2;        // + 64*i
    const int akq   = tid & 3;
    const int bk0   = tid >> 5;        // + 8*i
    const int bcq   = tid & 31;

#define GEMM_LDG(KK)                                                        \
    {                                                                       \
        aR[0] = *(const float4*)(E + (size_t)(v0 + arow0)      * HIDDEN + (KK) + akq * 4); \
        aR[1] = *(const float4*)(E + (size_t)(v0 + arow0 + 64) * HIDDEN + (KK) + akq * 4); \
        bR[0] = *(const float4*)(Wx + (size_t)((KK) + bk0)     * GWID + c0 + bcq * 4);     \
        bR[1] = *(const float4*)(Wx + (size_t)((KK) + bk0 + 8) * GWID + c0 + bcq * 4);     \
    }
#define GEMM_STS(BUF)                                                       \
    {                                                                       \
        As[BUF][akq * 4 + 0][arow0]      = aR[0].x;                         \
        As[BUF][akq * 4 + 1][arow0]      = aR[0].y;                         \
        As[BUF][akq * 4 + 2][arow0]      = aR[0].z;                         \
        As[BUF][akq * 4 + 3][arow0]      = aR[0].w;                         \
        As[BUF][akq * 4 + 0][arow0 + 64] = aR[1].x;                         \
        As[BUF][akq * 4 + 1][arow0 + 64] = aR[1].y;                         \
        As[BUF][akq * 4 + 2][arow0 + 64] = aR[1].z;                         \
        As[BUF][akq * 4 + 3][arow0 + 64] = aR[1].w;                         \
        *(float4*)&Bs[BUF][bk0][bcq * 4]     = bR[0];                       \
        *(float4*)&Bs[BUF][bk0 + 8][bcq * 4] = bR[1];                       \
    }

    GEMM_LDG(0);
    GEMM_STS(0);
    __syncthreads();

    for (int ch = 0; ch < 32; ++ch) {
        const int cur = ch & 1;
        if (ch + 1 < 32) GEMM_LDG((ch + 1) * 16);
#pragma unroll
        for (int k = 0; k < 16; ++k) {
            const float* ap = &As[cur][k][ty * 8];
            u64 a2[4];
            a2[0] = *(const u64*)(ap + 0);
            a2[1] = *(const u64*)(ap + 2);
            a2[2] = *(const u64*)(ap + 4);
            a2[3] = *(const u64*)(ap + 6);
            float b8[8];
            *(float4*)&b8[0] = *(const float4*)&Bs[cur][k][tx * 8];
            *(float4*)&b8[4] = *(const float4*)&Bs[cur][k][tx * 8 + 4];
            u64 w2[8];
#pragma unroll
            for (int j = 0; j < 8; ++j) SPLAT2(w2[j], b8[j]);
#pragma unroll
            for (int p = 0; p < 4; ++p)
#pragma unroll
                for (int j = 0; j < 8; ++j)
                    FMA2(acc2[p][j], a2[p], w2[j], acc2[p][j]);
        }
        if (ch + 1 < 32) GEMM_STS(cur ^ 1);
        __syncthreads();
    }

    float bias[8];
    {
        float4 x0 = *(const float4*)(bx + c0 + tx * 8);
        float4 x1 = *(const float4*)(bx + c0 + tx * 8 + 4);
        float4 h0v = *(const float4*)(bh + c0 + tx * 8);
        float4 h1v = *(const float4*)(bh + c0 + tx * 8 + 4);
        bias[0] = x0.x + h0v.x; bias[1] = x0.y + h0v.y;
        bias[2] = x0.z + h0v.z; bias[3] = x0.w + h0v.w;
        bias[4] = x1.x + h1v.x; bias[5] = x1.y + h1v.y;
        bias[6] = x1.z + h1v.z; bias[7] = x1.w + h1v.w;
    }
    float* Cbase = g_table + (size_t)d * VOCAB * GWID;
#pragma unroll
    for (int p = 0; p < 4; ++p) {
        float lo[8], hi[8];
#pragma unroll
        for (int j = 0; j < 8; ++j) UNPK2(lo[j], hi[j], acc2[p][j]);
        size_t r0 = (size_t)(v0 + ty * 8 + 2 * p) * GWID + c0 + tx * 8;
        float4 o;
        o = make_float4(lo[0]+bias[0], lo[1]+bias[1], lo[2]+bias[2], lo[3]+bias[3]);
        *(float4*)(Cbase + r0) = o;
        o = make_float4(lo[4]+bias[4], lo[5]+bias[5], lo[6]+bias[6], lo[7]+bias[7]);
        *(float4*)(Cbase + r0 + 4) = o;
        o = make_float4(hi[0]+bias[0], hi[1]+bias[1], hi[2]+bias[2], hi[3]+bias[3]);
        *(float4*)(Cbase + r0 + GWID) = o;
        o = make_float4(hi[4]+bias[4], hi[5]+bias[5], hi[6]+bias[6], hi[7]+bias[7]);
        *(float4*)(Cbase + r0 + GWID + 4) = o;
    }
}

// ---------------- persistent bidirectional LSTM recurrence ---------------------
// 128 CTAs x 256 threads (8 warps). CTA: dir = bid>>6, hidden units K0..K0+7.
// NO cross-warp reduce: warp w computes 128 gate outputs (8 batches x 16 cols)
// over the FULL r=512. h split into 8 chunks of 64 rows; warp w stages chunk w
// (polls its 8 producer CTAs), raises an smem flag; warps FMA chunks in
// staggered order w, w+1, ... (fp sum order change only).
#define SM_WS    0
#define SM_HS    16384
#define SM_GB    32768                 /* [32][36]  = 1152 */
#define SM_CS    (SM_GB + 32*36)       /* [8][33]   = 264  */
#define SM_HOUT  (SM_CS + 8*33)        /* [32][8]   = 256  */
#define SM_FLG   (SM_HOUT + 32*8)      /* 8 flags          */
#define SM_FLOATS (SM_FLG + 8)         /* 34456 floats = 137824 B */

__global__ void __launch_bounds__(256, 1) rnn_kernel(
    const void* __restrict__ tokens_raw,
    const float* __restrict__ h0,
    const float* __restrict__ wh_f,
    const float* __restrict__ wh_b,
    float* __restrict__ out)
{
    extern __shared__ float smem[];
    float* ws   = smem + SM_WS;
    float* hs   = smem + SM_HS;
    float* gbuf = smem + SM_GB;
    float* cs   = smem + SM_CS;
    float* hout = smem + SM_HOUT;
    volatile unsigned* flg = (volatile unsigned*)(smem + SM_FLG);

    const int tid = threadIdx.x;
    const int dir = blockIdx.x >> 6;
    const int myCta = blockIdx.x & 63;
    const int K0  = myCta * 8;
    const float* wh = dir ? wh_b : wh_f;

    // wh slice: ws[r*32 + g*8 + j] = wh[r][g*512 + K0 + j]
    for (int i = tid; i < 16384; i += 256) {
        int r = i >> 5, c = i & 31;
        int g = c >> 3, j = c & 7;
        ws[i] = wh[(size_t)r * GWID + g * HIDDEN + K0 + j];
    }
    {   // cell state init: c0 = h0
        int j = tid >> 5, b = tid & 31;
        cs[j * 33 + b] = h0[b * HIDDEN + K0 + j];
    }
    if (tid < 8) ((unsigned*)flg)[tid] = 0;
    __syncthreads();

    const int tok64 = g_tok64;
    const float* table = g_table + (size_t)dir * VOCAB * GWID;
    float* hb0 = &g_hbuf[dir][0][0];
    float* hb1 = &g_hbuf[dir][1][0];
    volatile unsigned* prog = &g_prog[dir][0][0];   // stride 32 u32 per CTA
    const uint32_t hs_u32 = (uint32_t)__cvta_generic_to_shared(hs);

    const int w  = tid >> 5, l = tid & 31;     // warp, lane
    const int pi = (w & 3) * 4 + (l & 3);      // batch-pair index: batches 2pi,2pi+1
    const int ci = (w >> 2) * 8 + (l >> 2);    // col-pair index:   cols 2ci,2ci+1
    // gx column mapping for cols (2ci, 2ci+1): same gate, adjacent
    const int gxcol = ((2 * ci) >> 3) * HIDDEN + K0 + ((2 * ci) & 7);

#define FMA_CHUNK64(G)                                                  \
    {                                                                   \
        const float* hp = hs + (G) * 2048 + 2 * pi;                     \
        const float* wp = ws + (G) * 2048 + 2 * ci;                     \
        _Pragma("unroll 8")                                             \
        for (int r = 0; r < 64; ++r) {                                  \
            u64 h2 = *(const u64*)(hp);                                 \
            float2 wv = *(const float2*)(wp);                           \
            u64 wa, wb;                                                 \
            SPLAT2(wa, wv.x); SPLAT2(wb, wv.y);                         \
            FMA2(acc0, h2, wa, acc0);                                   \
            FMA2(acc1, h2, wb, acc1);                                   \
            hp += 32; wp += 32;                                         \
        }                                                               \
    }

    int buf = 0;
    for (int s = 0; s < SEQ_LEN; ++s) {
        const int t = dir ? (SEQ_LEN - 1 - s) : s;

        // ---- top sync: prev cell writes (h, hout, cs) complete CTA-wide
        __syncthreads();

        // ---- publish h(s-1) (warp 7 lane 0: disjoint from warp 0's staging)
        if (tid == 224 && s > 0) {
            __threadfence();
            prog[myCta * 32] = (unsigned)s;
        }
        // ---- prev-step output write (warps 4-5)
        if (tid >= 128 && tid < 192 && s > 0) {
            const int tp = dir ? (SEQ_LEN - s) : (s - 1);
            int q = tid - 128;
            int b2 = q >> 1, half = q & 1;
            float4 v = *(float4*)(hout + b2 * 8 + half * 4);
            *(float4*)(out + (size_t)b2 * (SEQ_LEN * 1024)
                           + (size_t)tp * 1024 + dir * 512 + K0 + half * 4) = v;
        }

        // ---- gx prefetch for this thread's 2 batches x 2 cols (hidden by FMA)
        long long tk0, tk1;
        if (tok64) {
            longlong2 tt = *(const longlong2*)((const long long*)tokens_raw
                                               + (size_t)t * BATCHSZ + 2 * pi);
            tk0 = tt.x; tk1 = tt.y;
        } else {
            int2 tt = *(const int2*)((const int*)tokens_raw
                                     + (size_t)t * BATCHSZ + 2 * pi);
            tk0 = tt.x; tk1 = tt.y;
        }
        float2 gx0 = *(const float2*)(table + (size_t)tk0 * GWID + gxcol);
        float2 gx1 = *(const float2*)(table + (size_t)tk1 * GWID + gxcol);

        // ---- stage chunk w: poll its 8 producer CTAs, cp.async 8KB, flag
        {
            bool rdy;
            do {
                rdy = (l < 8) ? (prog[(8 * w + l) * 32] >= (unsigned)s) : true;
            } while (!__all_sync(0xffffffffu, rdy));

            const float4* src = (const float4*)(buf ? hb1 : hb0) + w * 512;
            const uint32_t dst = hs_u32 + w * 8192;
#pragma unroll
            for (int q = 0; q < 16; ++q)
                CPASYNC16(dst + (q * 32 + l) * 16, src + q * 32 + l);
            CPCOMMIT();
            CPWAIT(0);
            asm volatile("membar.cta;");
            __syncwarp();
            if (l == 0) flg[w] = (unsigned)(s + 1);
        }

        // ---- FMA all 8 chunks, staggered start at own chunk
        u64 acc0 = 0ull, acc1 = 0ull;
#pragma unroll 1
        for (int k = 0; k < 8; ++k) {
            const int g = (w + k) & 7;
            if (k > 0) {
                while (flg[g] < (unsigned)(s + 1)) { }
                __syncwarp();
            }
            FMA_CHUNK64(g);
        }

        // ---- gather: add gx, store 4 gate values to gbuf
        {
            float b0c0, b1c0, b0c1, b1c1;
            UNPK2(b0c0, b1c0, acc0);
            UNPK2(b0c1, b1c1, acc1);
            float2 v0 = make_float2(b0c0 + gx0.x, b0c1 + gx0.y);
            float2 v1 = make_float2(b1c0 + gx1.x, b1c1 + gx1.y);
            *(float2*)(gbuf + (2 * pi)     * 36 + 2 * ci) = v0;
            *(float2*)(gbuf + (2 * pi + 1) * 36 + 2 * ci) = v1;
        }
        __syncthreads();

        // ---- LSTM cell (256 cells, 1 per thread), fast transcendentals
        {
            float* hdst = buf ? hb0 : hb1;
            int j = tid >> 5, b = tid & 31;
            float ig = gbuf[b * 36 + j];
            float fg = gbuf[b * 36 + 8 + j];
            float gg = gbuf[b * 36 + 16 + j];
            float og = gbuf[b * 36 + 24 + j];
            float iv = sigmoid_fast(ig);
            float fv = sigmoid_fast(fg);
            float ov = sigmoid_fast(og);
            float gv = tanh_fast(gg);
            float c2 = fv * cs[j * 33 + b] + iv * gv;
            cs[j * 33 + b] = c2;
            float h2 = ov * tanh_fast(c2);
            hdst[(K0 + j) * BATCHSZ + b] = h2;
            hout[b * 8 + j] = h2;
        }
        buf ^= 1;
    }

    // ---- final step's output write
    __syncthreads();
    if (tid < 64) {
        const int tl = dir ? 0 : (SEQ_LEN - 1);
        int b2 = tid >> 1, half = tid & 1;
        float4 v = *(float4*)(hout + b2 * 8 + half * 4);
        *(float4*)(out + (size_t)b2 * (SEQ_LEN * 1024)
                       + (size_t)tl * 1024 + dir * 512 + K0 + half * 4) = v;
    }
}

// ---------------- launch --------------------------------------------------------
extern "C" void kernel_launch(void* const* d_in, const int* in_sizes, int n_in,
                              void* d_out, int out_size)
{
    const void*  tokens = d_in[0];
    const float* h0     = (const float*)d_in[1];
    const float* emb    = (const float*)d_in[2];
    const float* wx_f   = (const float*)d_in[3];
    const float* bx_f   = (const float*)d_in[4];
    const float* wh_f   = (const float*)d_in[5];
    const float* bh_f   = (const float*)d_in[6];
    const float* wx_b   = (const float*)d_in[7];
    const float* bx_b   = (const float*)d_in[8];
    const float* wh_b   = (const float*)d_in[9];
    const float* bh_b   = (const float*)d_in[10];
    float* out = (float*)d_out;

    cudaFuncSetAttribute(rnn_kernel, cudaFuncAttributeMaxDynamicSharedMemorySize,
                         SM_FLOATS * (int)sizeof(float));

    // 1) vocab gate table (parallel GEMM, 128x128 tiles)
    dim3 gg(GWID / 128, VOCAB / 128, 2);
    gx_gemm_kernel<<<gg, 256>>>(emb, wx_f, bx_f, bh_f, wx_b, bx_b, bh_b);

    // 2) reset progress counters, seed h, detect token dtype
    init_kernel<<<128, 256>>>((const int*)tokens, h0);

    // 3) persistent recurrence
    rnn_kernel<<<NCTA, 256, SM_FLOATS * (int)sizeof(float)>>>(
        tokens, h0, wh_f, wh_b, out);
}